// round 1
// baseline (speedup 1.0000x reference)
#include <cuda_runtime.h>
#include <cuda_bf16.h>
#include <cstdint>

// Problem constants (fixed by the dataset)
#define NUSER 200000
#define NITEM 200000
#define NN    400000           // NUSER + NITEM
#define EDIR  4000000          // directed edges (2 * E_HALF)
#define DF    384
#define RK    128
#define DL    64

typedef unsigned long long ull;

// ---------------- scratch (device globals; no allocations allowed) ----------
__device__ float g_ab[(size_t)NITEM * RK];   // (F@Wu^T)*(F@Wv^T)      102.4 MB
__device__ float g_x[(size_t)NN * DL];       // normalized node feats  102.4 MB
__device__ float g_h[(size_t)NN * DL];       // first GCN layer out    102.4 MB
__device__ float g_dinv[NN];                 // deg^-1/2
__device__ float g_coef[EDIR];               // per-edge norm coef      16   MB

// ---------------- packed fp32x2 helpers (FFMA2 path) ------------------------
__device__ __forceinline__ ull pk2(float x) {
    ull r;
    asm("mov.b64 %0, {%1, %1};" : "=l"(r) : "r"(__float_as_uint(x)));
    return r;
}
__device__ __forceinline__ void fma2(ull& d, ull a, ull b) {
    asm("fma.rn.f32x2 %0, %1, %2, %0;" : "+l"(d) : "l"(a), "l"(b));
}
__device__ __forceinline__ ull mul2(ull a, ull b) {
    ull r;
    asm("mul.rn.f32x2 %0, %1, %2;" : "=l"(r) : "l"(a), "l"(b));
    return r;
}

// ---------------- zero scratch ----------------------------------------------
__global__ void k_zero() {
    size_t stride = (size_t)gridDim.x * blockDim.x;
    size_t i = (size_t)blockIdx.x * blockDim.x + threadIdx.x;
    float4 z = make_float4(0.f, 0.f, 0.f, 0.f);
    size_t nh4 = (size_t)NN * DL / 4;
    float4* h4 = reinterpret_cast<float4*>(g_h);
    for (size_t j = i; j < nh4; j += stride) h4[j] = z;
    size_t nd4 = NN / 4;
    float4* d4 = reinterpret_cast<float4*>(g_dinv);
    for (size_t j = i; j < nd4; j += stride) d4[j] = z;
}

// ---------------- fused ab = (F@Wu^T) * (F@Wv^T) -----------------------------
// BM=64 rows, BN=128 (all cols), BK=16, 256 threads, thread tile 4 rows x 8 cols
// per matrix, accumulators packed as f32x2 pairs.
__global__ __launch_bounds__(256) void k_gemm_ab(const float* __restrict__ F,
                                                 const float* __restrict__ Wu,
                                                 const float* __restrict__ Wv) {
    __shared__ __align__(16) float Fs[16][64];
    __shared__ __align__(16) float Us[16][128];
    __shared__ __align__(16) float Vs[16][128];

    const int tid = threadIdx.x;
    const int tx = tid & 15;        // col group: cols [tx*8, tx*8+8)
    const int ty = tid >> 4;        // row group: rows [ty*4, ty*4+4)
    const int rowBase = blockIdx.x * 64;

    ull accU[4][4], accV[4][4];     // [row][colpair]
#pragma unroll
    for (int r = 0; r < 4; r++)
#pragma unroll
        for (int c = 0; c < 4; c++) { accU[r][c] = 0ull; accV[r][c] = 0ull; }

    const int fm = tid >> 2;              // 0..63
    const int fk = (tid & 3) * 4;         // 0,4,8,12
    const int wn = tid >> 1;              // 0..127
    const int wk = (tid & 1) * 8;         // 0,8

    for (int kk = 0; kk < DF; kk += 16) {
        // load F tile (transposed into Fs[k][m])
        float4 f4 = *reinterpret_cast<const float4*>(
            &F[(size_t)(rowBase + fm) * DF + kk + fk]);
        Fs[fk + 0][fm] = f4.x; Fs[fk + 1][fm] = f4.y;
        Fs[fk + 2][fm] = f4.z; Fs[fk + 3][fm] = f4.w;
        // load Wu / Wv tiles (transposed)
        float4 u0 = *reinterpret_cast<const float4*>(&Wu[(size_t)wn * DF + kk + wk]);
        float4 u1 = *reinterpret_cast<const float4*>(&Wu[(size_t)wn * DF + kk + wk + 4]);
        Us[wk + 0][wn] = u0.x; Us[wk + 1][wn] = u0.y; Us[wk + 2][wn] = u0.z; Us[wk + 3][wn] = u0.w;
        Us[wk + 4][wn] = u1.x; Us[wk + 5][wn] = u1.y; Us[wk + 6][wn] = u1.z; Us[wk + 7][wn] = u1.w;
        float4 v0 = *reinterpret_cast<const float4*>(&Wv[(size_t)wn * DF + kk + wk]);
        float4 v1 = *reinterpret_cast<const float4*>(&Wv[(size_t)wn * DF + kk + wk + 4]);
        Vs[wk + 0][wn] = v0.x; Vs[wk + 1][wn] = v0.y; Vs[wk + 2][wn] = v0.z; Vs[wk + 3][wn] = v0.w;
        Vs[wk + 4][wn] = v1.x; Vs[wk + 5][wn] = v1.y; Vs[wk + 6][wn] = v1.z; Vs[wk + 7][wn] = v1.w;
        __syncthreads();

#pragma unroll
        for (int k = 0; k < 16; k++) {
            float4 av = *reinterpret_cast<const float4*>(&Fs[k][ty * 4]);
            ull a0 = pk2(av.x), a1 = pk2(av.y), a2 = pk2(av.z), a3 = pk2(av.w);
            const ull* up = reinterpret_cast<const ull*>(&Us[k][tx * 8]);
            const ull* vp = reinterpret_cast<const ull*>(&Vs[k][tx * 8]);
            ull b0 = up[0], b1 = up[1], b2 = up[2], b3 = up[3];
            ull c0 = vp[0], c1 = vp[1], c2 = vp[2], c3 = vp[3];
            fma2(accU[0][0], a0, b0); fma2(accU[0][1], a0, b1);
            fma2(accU[0][2], a0, b2); fma2(accU[0][3], a0, b3);
            fma2(accU[1][0], a1, b0); fma2(accU[1][1], a1, b1);
            fma2(accU[1][2], a1, b2); fma2(accU[1][3], a1, b3);
            fma2(accU[2][0], a2, b0); fma2(accU[2][1], a2, b1);
            fma2(accU[2][2], a2, b2); fma2(accU[2][3], a2, b3);
            fma2(accU[3][0], a3, b0); fma2(accU[3][1], a3, b1);
            fma2(accU[3][2], a3, b2); fma2(accU[3][3], a3, b3);
            fma2(accV[0][0], a0, c0); fma2(accV[0][1], a0, c1);
            fma2(accV[0][2], a0, c2); fma2(accV[0][3], a0, c3);
            fma2(accV[1][0], a1, c0); fma2(accV[1][1], a1, c1);
            fma2(accV[1][2], a1, c2); fma2(accV[1][3], a1, c3);
            fma2(accV[2][0], a2, c0); fma2(accV[2][1], a2, c1);
            fma2(accV[2][2], a2, c2); fma2(accV[2][3], a2, c3);
            fma2(accV[3][0], a3, c0); fma2(accV[3][1], a3, c1);
            fma2(accV[3][2], a3, c2); fma2(accV[3][3], a3, c3);
        }
        __syncthreads();
    }

    // ab = a*b, store packed pairs
#pragma unroll
    for (int r = 0; r < 4; r++) {
        size_t rowOff = (size_t)(rowBase + ty * 4 + r) * RK + tx * 8;
#pragma unroll
        for (int c = 0; c < 4; c++) {
            ull p = mul2(accU[r][c], accV[r][c]);
            *reinterpret_cast<ull*>(&g_ab[rowOff + c * 2]) = p;
        }
    }
}

// ---------------- z = ab@Wproj^T -> transform -> item x rows -----------------
// BM=64 items, BN=64 (all cols), BK=16, 256 threads, 4x4 tile per thread.
__global__ __launch_bounds__(256) void k_proj(const float* __restrict__ Wproj,
                                              const float* __restrict__ id_emb) {
    __shared__ __align__(16) float As[16][64];
    __shared__ __align__(16) float Ws[16][64];

    const int tid = threadIdx.x;
    const int tx = tid & 15;      // cols [tx*4, tx*4+4)
    const int ty = tid >> 4;      // rows [ty*4, ty*4+4)
    const int ib = blockIdx.x * 64;

    float acc[4][4];
#pragma unroll
    for (int r = 0; r < 4; r++)
#pragma unroll
        for (int c = 0; c < 4; c++) acc[r][c] = 0.f;

    const int lm = tid >> 2;             // 0..63
    const int lk = (tid & 3) * 4;        // 0,4,8,12

    for (int kk = 0; kk < RK; kk += 16) {
        float4 a4 = *reinterpret_cast<const float4*>(
            &g_ab[(size_t)(ib + lm) * RK + kk + lk]);
        As[lk + 0][lm] = a4.x; As[lk + 1][lm] = a4.y;
        As[lk + 2][lm] = a4.z; As[lk + 3][lm] = a4.w;
        float4 w4 = *reinterpret_cast<const float4*>(
            &Wproj[(size_t)lm * RK + kk + lk]);
        Ws[lk + 0][lm] = w4.x; Ws[lk + 1][lm] = w4.y;
        Ws[lk + 2][lm] = w4.z; Ws[lk + 3][lm] = w4.w;
        __syncthreads();
#pragma unroll
        for (int k = 0; k < 16; k++) {
            float4 av = *reinterpret_cast<const float4*>(&As[k][ty * 4]);
            float4 wv = *reinterpret_cast<const float4*>(&Ws[k][tx * 4]);
            float aR[4] = {av.x, av.y, av.z, av.w};
            float wC[4] = {wv.x, wv.y, wv.z, wv.w};
#pragma unroll
            for (int r = 0; r < 4; r++)
#pragma unroll
                for (int c = 0; c < 4; c++) acc[r][c] += aR[r] * wC[c];
        }
        __syncthreads();
    }

    // signed sqrt
    float zr[4][4];
#pragma unroll
    for (int r = 0; r < 4; r++)
#pragma unroll
        for (int c = 0; c < 4; c++) {
            float z = acc[r][c];
            float s = sqrtf(fabsf(z) + 1e-9f);
            zr[r][c] = (z > 0.f) ? s : ((z < 0.f) ? -s : 0.f);
        }

    // l2norm(z) per item row (reduce over 16 tx-lanes within half-warp)
    float inv1[4];
#pragma unroll
    for (int r = 0; r < 4; r++) {
        float ss = zr[r][0] * zr[r][0] + zr[r][1] * zr[r][1] +
                   zr[r][2] * zr[r][2] + zr[r][3] * zr[r][3];
#pragma unroll
        for (int o = 8; o >= 1; o >>= 1) ss += __shfl_xor_sync(0xffffffffu, ss, o);
        inv1[r] = 1.f / fmaxf(sqrtf(ss), 1e-12f);
    }

    // temp = id_emb * z_norm ; then l2norm(temp) -> x
#pragma unroll
    for (int r = 0; r < 4; r++) {
        int item = ib + ty * 4 + r;
        float4 e4 = *reinterpret_cast<const float4*>(&id_emb[(size_t)item * DL + tx * 4]);
        float t0 = e4.x * zr[r][0] * inv1[r];
        float t1 = e4.y * zr[r][1] * inv1[r];
        float t2 = e4.z * zr[r][2] * inv1[r];
        float t3 = e4.w * zr[r][3] * inv1[r];
        float ss = t0 * t0 + t1 * t1 + t2 * t2 + t3 * t3;
#pragma unroll
        for (int o = 8; o >= 1; o >>= 1) ss += __shfl_xor_sync(0xffffffffu, ss, o);
        float inv2 = 1.f / fmaxf(sqrtf(ss), 1e-12f);
        float4 xv = make_float4(t0 * inv2, t1 * inv2, t2 * inv2, t3 * inv2);
        *reinterpret_cast<float4*>(&g_x[(size_t)(NUSER + item) * DL + tx * 4]) = xv;
    }
}

// ---------------- user rows: x = l2norm(preference); pref passthrough --------
__global__ __launch_bounds__(256) void k_user(const float* __restrict__ pref,
                                              float* __restrict__ out) {
    int w = threadIdx.x >> 5;
    int lane = threadIdx.x & 31;
    int row = blockIdx.x * 8 + w;
    if (row >= NUSER) return;
    float2 p = *reinterpret_cast<const float2*>(&pref[(size_t)row * DL + lane * 2]);
    float ss = p.x * p.x + p.y * p.y;
#pragma unroll
    for (int o = 16; o >= 1; o >>= 1) ss += __shfl_xor_sync(0xffffffffu, ss, o);
    float inv = 1.f / fmaxf(sqrtf(ss), 1e-12f);
    *reinterpret_cast<float2*>(&g_x[(size_t)row * DL + lane * 2]) =
        make_float2(p.x * inv, p.y * inv);
    // passthrough output: preference
    *reinterpret_cast<float2*>(&out[(size_t)NN * DL + (size_t)row * DL + lane * 2]) = p;
}

// ---------------- degree / norm coef -----------------------------------------
__global__ __launch_bounds__(256) void k_deg(const int* __restrict__ ei) {
    int e = blockIdx.x * 256 + threadIdx.x;
    if (e < EDIR) atomicAdd(&g_dinv[ei[e]], 1.0f);
}
__global__ __launch_bounds__(256) void k_fin_deg() {
    int i = blockIdx.x * 256 + threadIdx.x;
    if (i < NN) {
        float d = g_dinv[i];
        g_dinv[i] = (d > 0.f) ? rsqrtf(d) : 0.f;
    }
}
__global__ __launch_bounds__(256) void k_coef(const int* __restrict__ ei) {
    int e = blockIdx.x * 256 + threadIdx.x;
    if (e < EDIR) g_coef[e] = g_dinv[ei[e]] * g_dinv[ei[EDIR + e]];
}

// ---------------- GCN scatter layer ------------------------------------------
// mode 0: g_h    += coef * g_x[row]   (g_h pre-zeroed)
// mode 1: outdst += coef * g_h[row]   (outdst pre-filled with x + h)
__global__ __launch_bounds__(256) void k_layer(const int* __restrict__ ei,
                                               float* __restrict__ outdst,
                                               int mode) {
    long long t = (long long)blockIdx.x * 256 + threadIdx.x;
    int e = (int)(t >> 4);
    if (e >= EDIR) return;
    int lane = (int)t & 15;
    int r = ei[e];
    int c = ei[EDIR + e];
    float cf = g_coef[e];
    const float* src = mode ? g_h : g_x;
    float* dst = mode ? outdst : g_h;
    float4 v = *reinterpret_cast<const float4*>(&src[(size_t)r * DL + lane * 4]);
    float4 m4 = make_float4(cf * v.x, cf * v.y, cf * v.z, cf * v.w);
    atomicAdd(reinterpret_cast<float4*>(&dst[(size_t)c * DL + lane * 4]), m4);
}

// ---------------- out = x + h (then layer 2 accumulates h1 on top) -----------
__global__ __launch_bounds__(256) void k_prefill(float* __restrict__ out) {
    int i = blockIdx.x * 256 + threadIdx.x;   // float4 index, < NN*DL/4 = 6.4M
    const float4* x4 = reinterpret_cast<const float4*>(g_x);
    const float4* h4 = reinterpret_cast<const float4*>(g_h);
    float4 a = x4[i], b = h4[i];
    reinterpret_cast<float4*>(out)[i] =
        make_float4(a.x + b.x, a.y + b.y, a.z + b.z, a.w + b.w);
}

// ---------------- launch ------------------------------------------------------
extern "C" void kernel_launch(void* const* d_in, const int* in_sizes, int n_in,
                              void* d_out, int out_size) {
    const int*   ei     = (const int*)d_in[0];     // [2, 4M]
    const float* F      = (const float*)d_in[1];   // [200000, 384]
    const float* Wu     = (const float*)d_in[2];   // [128, 384]
    const float* Wv     = (const float*)d_in[3];   // [128, 384]
    const float* Wproj  = (const float*)d_in[4];   // [64, 128]
    const float* id_emb = (const float*)d_in[5];   // [200000, 64]
    const float* pref   = (const float*)d_in[6];   // [200000, 64]
    float* out = (float*)d_out;                    // [400000*64 + 200000*64]

    k_zero<<<4096, 256>>>();                       // zero g_h, g_dinv
    k_gemm_ab<<<NITEM / 64, 256>>>(F, Wu, Wv);     // 3125 blocks
    k_proj<<<NITEM / 64, 256>>>(Wproj, id_emb);    // 3125 blocks
    k_user<<<NUSER / 8, 256>>>(pref, out);         // 25000 blocks
    k_deg<<<EDIR / 256, 256>>>(ei);                // 15625 blocks
    k_fin_deg<<<(NN + 255) / 256, 256>>>();
    k_coef<<<EDIR / 256, 256>>>(ei);
    k_layer<<<EDIR * 16 / 256, 256>>>(ei, out, 0); // h = A x
    k_prefill<<<NN * DL / 4 / 256, 256>>>(out);    // out = x + h
    k_layer<<<EDIR * 16 / 256, 256>>>(ei, out, 1); // out += A h
}

// round 2
// speedup vs baseline: 1.0911x; 1.0911x over previous
#include <cuda_runtime.h>
#include <cuda_bf16.h>
#include <cstdint>

// Problem constants (fixed by the dataset)
#define NUSER 200000
#define NITEM 200000
#define NN    400000           // NUSER + NITEM
#define EDIR  4000000          // directed edges (2 * E_HALF)
#define DF    384
#define RK    128
#define DL    64

#define SCAN_CHUNK 1024
#define NB_SCAN    ((NN + SCAN_CHUNK - 1) / SCAN_CHUNK)   // 391

typedef unsigned long long ull;

// ---------------- scratch (device globals; no allocations allowed) ----------
__device__ float g_ab[(size_t)NITEM * RK];   // (F@Wu^T)*(F@Wv^T)      102.4 MB
__device__ float g_x[(size_t)NN * DL];       // normalized node feats  102.4 MB
__device__ float g_h[(size_t)NN * DL];       // first GCN layer out    102.4 MB
__device__ int2  g_perm[EDIR];               // CSR: (src row, coef)    32   MB
__device__ int   g_cnt[NN];                  // per-node degree (hist)
__device__ int   g_off[NN];                  // CSR exclusive offsets
__device__ int   g_cursor[NN];               // scatter cursors
__device__ int   g_bsum[NB_SCAN];            // scan block sums
__device__ float g_dinv[NN];                 // deg^-1/2

// ---------------- packed fp32x2 helpers (FFMA2 path) ------------------------
__device__ __forceinline__ ull pk2(float x) {
    ull r;
    asm("mov.b64 %0, {%1, %1};" : "=l"(r) : "r"(__float_as_uint(x)));
    return r;
}
__device__ __forceinline__ void fma2(ull& d, ull a, ull b) {
    asm("fma.rn.f32x2 %0, %1, %2, %0;" : "+l"(d) : "l"(a), "l"(b));
}
__device__ __forceinline__ ull mul2(ull a, ull b) {
    ull r;
    asm("mul.rn.f32x2 %0, %1, %2;" : "=l"(r) : "l"(a), "l"(b));
    return r;
}

// ---------------- zero histogram ---------------------------------------------
__global__ void k_zero() {
    int i = blockIdx.x * 256 + threadIdx.x;
    if (i < NN) g_cnt[i] = 0;
}

// ---------------- fused ab = (F@Wu^T) * (F@Wv^T) -----------------------------
__global__ __launch_bounds__(256) void k_gemm_ab(const float* __restrict__ F,
                                                 const float* __restrict__ Wu,
                                                 const float* __restrict__ Wv) {
    __shared__ __align__(16) float Fs[16][64];
    __shared__ __align__(16) float Us[16][128];
    __shared__ __align__(16) float Vs[16][128];

    const int tid = threadIdx.x;
    const int tx = tid & 15;        // col group: cols [tx*8, tx*8+8)
    const int ty = tid >> 4;        // row group: rows [ty*4, ty*4+4)
    const int rowBase = blockIdx.x * 64;

    ull accU[4][4], accV[4][4];
#pragma unroll
    for (int r = 0; r < 4; r++)
#pragma unroll
        for (int c = 0; c < 4; c++) { accU[r][c] = 0ull; accV[r][c] = 0ull; }

    const int fm = tid >> 2;
    const int fk = (tid & 3) * 4;
    const int wn = tid >> 1;
    const int wk = (tid & 1) * 8;

    for (int kk = 0; kk < DF; kk += 16) {
        float4 f4 = *reinterpret_cast<const float4*>(
            &F[(size_t)(rowBase + fm) * DF + kk + fk]);
        Fs[fk + 0][fm] = f4.x; Fs[fk + 1][fm] = f4.y;
        Fs[fk + 2][fm] = f4.z; Fs[fk + 3][fm] = f4.w;
        float4 u0 = *reinterpret_cast<const float4*>(&Wu[(size_t)wn * DF + kk + wk]);
        float4 u1 = *reinterpret_cast<const float4*>(&Wu[(size_t)wn * DF + kk + wk + 4]);
        Us[wk + 0][wn] = u0.x; Us[wk + 1][wn] = u0.y; Us[wk + 2][wn] = u0.z; Us[wk + 3][wn] = u0.w;
        Us[wk + 4][wn] = u1.x; Us[wk + 5][wn] = u1.y; Us[wk + 6][wn] = u1.z; Us[wk + 7][wn] = u1.w;
        float4 v0 = *reinterpret_cast<const float4*>(&Wv[(size_t)wn * DF + kk + wk]);
        float4 v1 = *reinterpret_cast<const float4*>(&Wv[(size_t)wn * DF + kk + wk + 4]);
        Vs[wk + 0][wn] = v0.x; Vs[wk + 1][wn] = v0.y; Vs[wk + 2][wn] = v0.z; Vs[wk + 3][wn] = v0.w;
        Vs[wk + 4][wn] = v1.x; Vs[wk + 5][wn] = v1.y; Vs[wk + 6][wn] = v1.z; Vs[wk + 7][wn] = v1.w;
        __syncthreads();

#pragma unroll
        for (int k = 0; k < 16; k++) {
            float4 av = *reinterpret_cast<const float4*>(&Fs[k][ty * 4]);
            ull a0 = pk2(av.x), a1 = pk2(av.y), a2 = pk2(av.z), a3 = pk2(av.w);
            const ull* up = reinterpret_cast<const ull*>(&Us[k][tx * 8]);
            const ull* vp = reinterpret_cast<const ull*>(&Vs[k][tx * 8]);
            ull b0 = up[0], b1 = up[1], b2 = up[2], b3 = up[3];
            ull c0 = vp[0], c1 = vp[1], c2 = vp[2], c3 = vp[3];
            fma2(accU[0][0], a0, b0); fma2(accU[0][1], a0, b1);
            fma2(accU[0][2], a0, b2); fma2(accU[0][3], a0, b3);
            fma2(accU[1][0], a1, b0); fma2(accU[1][1], a1, b1);
            fma2(accU[1][2], a1, b2); fma2(accU[1][3], a1, b3);
            fma2(accU[2][0], a2, b0); fma2(accU[2][1], a2, b1);
            fma2(accU[2][2], a2, b2); fma2(accU[2][3], a2, b3);
            fma2(accU[3][0], a3, b0); fma2(accU[3][1], a3, b1);
            fma2(accU[3][2], a3, b2); fma2(accU[3][3], a3, b3);
            fma2(accV[0][0], a0, c0); fma2(accV[0][1], a0, c1);
            fma2(accV[0][2], a0, c2); fma2(accV[0][3], a0, c3);
            fma2(accV[1][0], a1, c0); fma2(accV[1][1], a1, c1);
            fma2(accV[1][2], a1, c2); fma2(accV[1][3], a1, c3);
            fma2(accV[2][0], a2, c0); fma2(accV[2][1], a2, c1);
            fma2(accV[2][2], a2, c2); fma2(accV[2][3], a2, c3);
            fma2(accV[3][0], a3, c0); fma2(accV[3][1], a3, c1);
            fma2(accV[3][2], a3, c2); fma2(accV[3][3], a3, c3);
        }
        __syncthreads();
    }

#pragma unroll
    for (int r = 0; r < 4; r++) {
        size_t rowOff = (size_t)(rowBase + ty * 4 + r) * RK + tx * 8;
#pragma unroll
        for (int c = 0; c < 4; c++) {
            ull p = mul2(accU[r][c], accV[r][c]);
            *reinterpret_cast<ull*>(&g_ab[rowOff + c * 2]) = p;
        }
    }
}

// ---------------- z = ab@Wproj^T -> transform -> item x rows -----------------
__global__ __launch_bounds__(256) void k_proj(const float* __restrict__ Wproj,
                                              const float* __restrict__ id_emb) {
    __shared__ __align__(16) float As[16][64];
    __shared__ __align__(16) float Ws[16][64];

    const int tid = threadIdx.x;
    const int tx = tid & 15;
    const int ty = tid >> 4;
    const int ib = blockIdx.x * 64;

    float acc[4][4];
#pragma unroll
    for (int r = 0; r < 4; r++)
#pragma unroll
        for (int c = 0; c < 4; c++) acc[r][c] = 0.f;

    const int lm = tid >> 2;
    const int lk = (tid & 3) * 4;

    for (int kk = 0; kk < RK; kk += 16) {
        float4 a4 = *reinterpret_cast<const float4*>(
            &g_ab[(size_t)(ib + lm) * RK + kk + lk]);
        As[lk + 0][lm] = a4.x; As[lk + 1][lm] = a4.y;
        As[lk + 2][lm] = a4.z; As[lk + 3][lm] = a4.w;
        float4 w4 = *reinterpret_cast<const float4*>(
            &Wproj[(size_t)lm * RK + kk + lk]);
        Ws[lk + 0][lm] = w4.x; Ws[lk + 1][lm] = w4.y;
        Ws[lk + 2][lm] = w4.z; Ws[lk + 3][lm] = w4.w;
        __syncthreads();
#pragma unroll
        for (int k = 0; k < 16; k++) {
            float4 av = *reinterpret_cast<const float4*>(&As[k][ty * 4]);
            float4 wv = *reinterpret_cast<const float4*>(&Ws[k][tx * 4]);
            float aR[4] = {av.x, av.y, av.z, av.w};
            float wC[4] = {wv.x, wv.y, wv.z, wv.w};
#pragma unroll
            for (int r = 0; r < 4; r++)
#pragma unroll
                for (int c = 0; c < 4; c++) acc[r][c] += aR[r] * wC[c];
        }
        __syncthreads();
    }

    float zr[4][4];
#pragma unroll
    for (int r = 0; r < 4; r++)
#pragma unroll
        for (int c = 0; c < 4; c++) {
            float z = acc[r][c];
            float s = sqrtf(fabsf(z) + 1e-9f);
            zr[r][c] = (z > 0.f) ? s : ((z < 0.f) ? -s : 0.f);
        }

    float inv1[4];
#pragma unroll
    for (int r = 0; r < 4; r++) {
        float ss = zr[r][0] * zr[r][0] + zr[r][1] * zr[r][1] +
                   zr[r][2] * zr[r][2] + zr[r][3] * zr[r][3];
#pragma unroll
        for (int o = 8; o >= 1; o >>= 1) ss += __shfl_xor_sync(0xffffffffu, ss, o);
        inv1[r] = 1.f / fmaxf(sqrtf(ss), 1e-12f);
    }

#pragma unroll
    for (int r = 0; r < 4; r++) {
        int item = ib + ty * 4 + r;
        float4 e4 = *reinterpret_cast<const float4*>(&id_emb[(size_t)item * DL + tx * 4]);
        float t0 = e4.x * zr[r][0] * inv1[r];
        float t1 = e4.y * zr[r][1] * inv1[r];
        float t2 = e4.z * zr[r][2] * inv1[r];
        float t3 = e4.w * zr[r][3] * inv1[r];
        float ss = t0 * t0 + t1 * t1 + t2 * t2 + t3 * t3;
#pragma unroll
        for (int o = 8; o >= 1; o >>= 1) ss += __shfl_xor_sync(0xffffffffu, ss, o);
        float inv2 = 1.f / fmaxf(sqrtf(ss), 1e-12f);
        float4 xv = make_float4(t0 * inv2, t1 * inv2, t2 * inv2, t3 * inv2);
        *reinterpret_cast<float4*>(&g_x[(size_t)(NUSER + item) * DL + tx * 4]) = xv;
    }
}

// ---------------- user rows: x = l2norm(preference); pref passthrough --------
__global__ __launch_bounds__(256) void k_user(const float* __restrict__ pref,
                                              float* __restrict__ out) {
    int w = threadIdx.x >> 5;
    int lane = threadIdx.x & 31;
    int row = blockIdx.x * 8 + w;
    if (row >= NUSER) return;
    float2 p = *reinterpret_cast<const float2*>(&pref[(size_t)row * DL + lane * 2]);
    float ss = p.x * p.x + p.y * p.y;
#pragma unroll
    for (int o = 16; o >= 1; o >>= 1) ss += __shfl_xor_sync(0xffffffffu, ss, o);
    float inv = 1.f / fmaxf(sqrtf(ss), 1e-12f);
    *reinterpret_cast<float2*>(&g_x[(size_t)row * DL + lane * 2]) =
        make_float2(p.x * inv, p.y * inv);
    *reinterpret_cast<float2*>(&out[(size_t)NN * DL + (size_t)row * DL + lane * 2]) = p;
}

// ---------------- histogram over row (== degree per node) --------------------
__global__ __launch_bounds__(256) void k_hist(const int* __restrict__ ei) {
    int e = blockIdx.x * 256 + threadIdx.x;
    if (e < EDIR) atomicAdd(&g_cnt[ei[e]], 1);
}

// ---------------- exclusive scan of g_cnt -> g_off (3 kernels) ---------------
__global__ __launch_bounds__(256) void k_scan_local() {
    __shared__ int warp_tot[8];
    const int tid = threadIdx.x;
    const int lane = tid & 31, wid = tid >> 5;
    const int base = blockIdx.x * SCAN_CHUNK + tid * 4;

    int4 v = make_int4(0, 0, 0, 0);
    if (base + 3 < NN) {
        v = *reinterpret_cast<const int4*>(&g_cnt[base]);
    } else {
        if (base + 0 < NN) v.x = g_cnt[base + 0];
        if (base + 1 < NN) v.y = g_cnt[base + 1];
        if (base + 2 < NN) v.z = g_cnt[base + 2];
        if (base + 3 < NN) v.w = g_cnt[base + 3];
    }
    int s0 = v.x, s1 = s0 + v.y, s2 = s1 + v.z, s3 = s2 + v.w;
    int s = s3;

    int incl = s;
#pragma unroll
    for (int o = 1; o < 32; o <<= 1) {
        int t = __shfl_up_sync(0xffffffffu, incl, o);
        if (lane >= o) incl += t;
    }
    if (lane == 31) warp_tot[wid] = incl;
    __syncthreads();
    if (wid == 0 && lane < 8) {
        int t = warp_tot[lane];
        int it = t;
#pragma unroll
        for (int o = 1; o < 8; o <<= 1) {
            int u = __shfl_up_sync(0xffu, it, o);
            if (lane >= o) it += u;
        }
        warp_tot[lane] = it - t;   // exclusive
    }
    __syncthreads();
    int excl = incl - s + warp_tot[wid];

    if (base + 0 < NN) g_off[base + 0] = excl;
    if (base + 1 < NN) g_off[base + 1] = excl + s0;
    if (base + 2 < NN) g_off[base + 2] = excl + s1;
    if (base + 3 < NN) g_off[base + 3] = excl + s2;
    if (tid == 255) g_bsum[blockIdx.x] = excl + s;
}

__global__ __launch_bounds__(512) void k_scan_bsum() {
    __shared__ int warp_tot[16];
    const int tid = threadIdx.x;
    const int lane = tid & 31, wid = tid >> 5;
    int v = (tid < NB_SCAN) ? g_bsum[tid] : 0;
    int incl = v;
#pragma unroll
    for (int o = 1; o < 32; o <<= 1) {
        int t = __shfl_up_sync(0xffffffffu, incl, o);
        if (lane >= o) incl += t;
    }
    if (lane == 31) warp_tot[wid] = incl;
    __syncthreads();
    if (wid == 0 && lane < 16) {
        int t = warp_tot[lane];
        int it = t;
#pragma unroll
        for (int o = 1; o < 16; o <<= 1) {
            int u = __shfl_up_sync(0xffffu, it, o);
            if (lane >= o) it += u;
        }
        warp_tot[lane] = it - t;
    }
    __syncthreads();
    int excl = incl - v + warp_tot[wid];
    if (tid < NB_SCAN) g_bsum[tid] = excl;
}

__global__ __launch_bounds__(256) void k_scan_add() {
    int i = blockIdx.x * 256 + threadIdx.x;
    if (i >= NN) return;
    int o = g_off[i] + g_bsum[i >> 10];
    g_off[i] = o;
    g_cursor[i] = o;
    int c = g_cnt[i];
    g_dinv[i] = (c > 0) ? rsqrtf((float)c) : 0.f;
}

// ---------------- CSR scatter: bucket edges by col, attach coef --------------
__global__ __launch_bounds__(256) void k_scatter(const int* __restrict__ ei) {
    int e = blockIdx.x * 256 + threadIdx.x;
    if (e >= EDIR) return;
    int r = ei[e];
    int c = ei[EDIR + e];
    int pos = atomicAdd(&g_cursor[c], 1);
    int2 p;
    p.x = r;
    p.y = __float_as_int(g_dinv[r] * g_dinv[c]);
    g_perm[pos] = p;
}

// ---------------- gather-style GCN layer (no atomics) ------------------------
// mode 0: g_h[node] = sum coef * g_x[src]
// mode 1: out[node] = g_x[node] + g_h[node] + sum coef * g_h[src]
__global__ __launch_bounds__(256) void k_layer_csr(float* __restrict__ out,
                                                   int mode) {
    int node = (blockIdx.x << 3) + (threadIdx.x >> 5);
    if (node >= NN) return;
    int lane = threadIdx.x & 31;
    int off = g_off[node];
    int cnt = g_cnt[node];
    const float* __restrict__ src = mode ? g_h : g_x;
    const int2* __restrict__ pp = g_perm + off;

    float2 acc = make_float2(0.f, 0.f);
    int j = 0;
    for (; j + 4 <= cnt; j += 4) {
        int2 p0 = pp[j + 0], p1 = pp[j + 1], p2 = pp[j + 2], p3 = pp[j + 3];
        float2 v0 = *reinterpret_cast<const float2*>(&src[(size_t)p0.x * DL + lane * 2]);
        float2 v1 = *reinterpret_cast<const float2*>(&src[(size_t)p1.x * DL + lane * 2]);
        float2 v2 = *reinterpret_cast<const float2*>(&src[(size_t)p2.x * DL + lane * 2]);
        float2 v3 = *reinterpret_cast<const float2*>(&src[(size_t)p3.x * DL + lane * 2]);
        float c0 = __int_as_float(p0.y), c1 = __int_as_float(p1.y);
        float c2 = __int_as_float(p2.y), c3 = __int_as_float(p3.y);
        acc.x += c0 * v0.x; acc.y += c0 * v0.y;
        acc.x += c1 * v1.x; acc.y += c1 * v1.y;
        acc.x += c2 * v2.x; acc.y += c2 * v2.y;
        acc.x += c3 * v3.x; acc.y += c3 * v3.y;
    }
    for (; j < cnt; j++) {
        int2 p = pp[j];
        float2 v = *reinterpret_cast<const float2*>(&src[(size_t)p.x * DL + lane * 2]);
        float cf = __int_as_float(p.y);
        acc.x += cf * v.x; acc.y += cf * v.y;
    }

    size_t o = (size_t)node * DL + lane * 2;
    if (mode == 0) {
        *reinterpret_cast<float2*>(&g_h[o]) = acc;
    } else {
        float2 xv = *reinterpret_cast<const float2*>(&g_x[o]);
        float2 hv = *reinterpret_cast<const float2*>(&g_h[o]);
        *reinterpret_cast<float2*>(&out[o]) =
            make_float2(xv.x + hv.x + acc.x, xv.y + hv.y + acc.y);
    }
}

// ---------------- launch ------------------------------------------------------
extern "C" void kernel_launch(void* const* d_in, const int* in_sizes, int n_in,
                              void* d_out, int out_size) {
    const int*   ei     = (const int*)d_in[0];     // [2, 4M]
    const float* F      = (const float*)d_in[1];   // [200000, 384]
    const float* Wu     = (const float*)d_in[2];   // [128, 384]
    const float* Wv     = (const float*)d_in[3];   // [128, 384]
    const float* Wproj  = (const float*)d_in[4];   // [64, 128]
    const float* id_emb = (const float*)d_in[5];   // [200000, 64]
    const float* pref   = (const float*)d_in[6];   // [200000, 64]
    float* out = (float*)d_out;

    k_zero<<<(NN + 255) / 256, 256>>>();
    k_hist<<<EDIR / 256, 256>>>(ei);
    k_gemm_ab<<<NITEM / 64, 256>>>(F, Wu, Wv);
    k_proj<<<NITEM / 64, 256>>>(Wproj, id_emb);
    k_user<<<NUSER / 8, 256>>>(pref, out);
    k_scan_local<<<NB_SCAN, 256>>>();
    k_scan_bsum<<<1, 512>>>();
    k_scan_add<<<(NN + 255) / 256, 256>>>();
    k_scatter<<<EDIR / 256, 256>>>(ei);
    k_layer_csr<<<NN / 8, 256>>>(out, 0);          // h = A x
    k_layer_csr<<<NN / 8, 256>>>(out, 1);          // out = x + h + A h
}